// round 1
// baseline (speedup 1.0000x reference)
#include <cuda_runtime.h>
#include <math_constants.h>

// Problem shape (fixed by dataset)
#define BB    64
#define CC    256
#define CS    64
#define HW    4096      // 64*64
#define NC    8
#define NCHAN (BB*CC)   // 16384

// Scratch (no allocations allowed in kernel_launch)
__device__ float g_pooled[NCHAN];
__device__ float g_chmin[NCHAN];
__device__ float g_chmax[NCHAN];
__device__ float g_scale[NCHAN];
__device__ float g_smin[BB];
__device__ float g_smax[BB];
__device__ float g_ss[BB];
__device__ float g_zz[BB];

// ---------------------------------------------------------------------------
// Kernel 1: per-channel sum/min/max of x.  One block per (b,c) channel,
// 4096 floats = 1024 float4, 256 threads * 4 iters, fully coalesced stream.
// ---------------------------------------------------------------------------
__global__ __launch_bounds__(256) void k_stats(const float4* __restrict__ x) {
    const int chan = blockIdx.x;
    const float4* p = x + (size_t)chan * (HW / 4);
    const int t = threadIdx.x;

    float s  = 0.0f;
    float mn = CUDART_INF_F;
    float mx = -CUDART_INF_F;
#pragma unroll
    for (int i = 0; i < HW / 4 / 256; ++i) {
        float4 v = p[t + i * 256];
        s += (v.x + v.y) + (v.z + v.w);
        mn = fminf(mn, fminf(fminf(v.x, v.y), fminf(v.z, v.w)));
        mx = fmaxf(mx, fmaxf(fmaxf(v.x, v.y), fmaxf(v.z, v.w)));
    }
#pragma unroll
    for (int off = 16; off; off >>= 1) {
        s  += __shfl_xor_sync(0xffffffffu, s, off);
        mn  = fminf(mn, __shfl_xor_sync(0xffffffffu, mn, off));
        mx  = fmaxf(mx, __shfl_xor_sync(0xffffffffu, mx, off));
    }
    __shared__ float ws[8], wmn[8], wmx[8];
    if ((t & 31) == 0) { ws[t >> 5] = s; wmn[t >> 5] = mn; wmx[t >> 5] = mx; }
    __syncthreads();
    if (t == 0) {
        float S = 0.0f, MN = CUDART_INF_F, MX = -CUDART_INF_F;
#pragma unroll
        for (int j = 0; j < 8; ++j) {
            S += ws[j];
            MN = fminf(MN, wmn[j]);
            MX = fmaxf(MX, wmx[j]);
        }
        g_pooled[chan] = S * (1.0f / (float)HW);   // /4096 exact (pow2)
        g_chmin[chan]  = MN;
        g_chmax[chan]  = MX;
    }
}

// ---------------------------------------------------------------------------
// Kernel 2: SE MLP + hardsigmoid + per-sample min/max of out=scale*x.
// One block per batch sample b.  scale>=0, so channel min/max of out is
// scale * (channel min/max of x).
// ---------------------------------------------------------------------------
__global__ __launch_bounds__(256) void k_se(const float* __restrict__ w1,
                                            const float* __restrict__ b1,
                                            const float* __restrict__ w2,
                                            const float* __restrict__ b2) {
    const int b = blockIdx.x;
    const int t = threadIdx.x;

    __shared__ float sp[CC];
    __shared__ float sh[CS];
    sp[t] = g_pooled[b * CC + t];
    __syncthreads();

    // h[s] = relu(sum_c pooled[c]*w1[s,c] + b1[s]); 4 threads per s.
    const int si = t >> 2;
    const int r  = t & 3;
    float acc = 0.0f;
    const float* wrow = w1 + si * CC + r * 64;
    const float* prow = sp + r * 64;
#pragma unroll 8
    for (int c = 0; c < 64; ++c) acc += prow[c] * wrow[c];
    acc += __shfl_xor_sync(0xffffffffu, acc, 1);
    acc += __shfl_xor_sync(0xffffffffu, acc, 2);
    if (r == 0) sh[si] = fmaxf(acc + b1[si], 0.0f);
    __syncthreads();

    // v[c] = sum_s h[s]*w2[c,s] + b2[c]; one thread per c.
    float v = b2[t];
    const float* w2row = w2 + t * CS;
#pragma unroll 8
    for (int s = 0; s < CS; ++s) v += sh[s] * w2row[s];

    const float sc = fminf(fmaxf(v / 6.0f + 0.5f, 0.0f), 1.0f);  // hardsigmoid
    g_scale[b * CC + t] = sc;

    // per-sample min/max of out (scale >= 0)
    float cmn = sc * g_chmin[b * CC + t];
    float cmx = sc * g_chmax[b * CC + t];

    __shared__ float rmn[256], rmx[256];
    rmn[t] = cmn; rmx[t] = cmx;
    __syncthreads();
    for (int off = 128; off; off >>= 1) {
        if (t < off) {
            rmn[t] = fminf(rmn[t], rmn[t + off]);
            rmx[t] = fmaxf(rmx[t], rmx[t + off]);
        }
        __syncthreads();
    }
    if (t == 0) { g_smin[b] = rmn[0]; g_smax[b] = rmx[0]; }
}

// ---------------------------------------------------------------------------
// Kernel 3: per-cluster segment min/max + EMA + quant params, gather per-sample.
// Tiny (1 block, 64 threads).
// ---------------------------------------------------------------------------
__global__ void k_qparams(const int* __restrict__ sample_cluster,
                          const float* __restrict__ act_range) {
    const int t = threadIdx.x;
    __shared__ float s_s[NC], s_z[NC];
    __shared__ int   s_cl[BB];
    if (t < BB) s_cl[t] = sample_cluster[t];
    __syncthreads();

    if (t < NC) {
        float cmin = CUDART_INF_F, cmax = -CUDART_INF_F;
        for (int i = 0; i < BB; ++i) {
            if (s_cl[i] == t) {
                cmin = fminf(cmin, g_smin[i]);
                cmax = fmaxf(cmax, g_smax[i]);
            }
        }
        // EMA update (empty clusters produce inf/nan here but are never gathered)
        float nm = act_range[2 * t]     * 0.995f + cmin * 0.005f;
        float nM = act_range[2 * t + 1] * 0.995f + cmax * 0.005f;
        float s  = (nM - nm) / 255.0f;
        float z  = -rintf(nm / s);
        s_s[t] = s;
        s_z[t] = z;
    }
    __syncthreads();
    if (t < BB) {
        int k = s_cl[t];
        g_ss[t] = s_s[k];
        g_zz[t] = s_z[k];
    }
}

// ---------------------------------------------------------------------------
// Kernel 4: fused scale + fake-quant.  One block per channel, float4 stream.
// out = (clip(rint(sc*x / s + z), 0, 255) - z) * s
// Division done as reciprocal-multiply + one FMA Newton step (faithfully
// rounded, avoids per-element MUFU div).
// ---------------------------------------------------------------------------
__device__ __forceinline__ float fakequant1(float xv, float sc, float s,
                                            float inv_s, float z) {
    float o = sc * xv;
    float d = o * inv_s;
    d = fmaf(fmaf(-s, d, o), inv_s, d);           // refine o/s
    float q = fminf(fmaxf(rintf(d + z), 0.0f), 255.0f);
    return (q - z) * s;
}

__global__ __launch_bounds__(256) void k_quant(const float4* __restrict__ x,
                                               float4* __restrict__ out) {
    const int chan = blockIdx.x;
    const int b    = chan >> 8;          // chan / CC
    const float sc    = g_scale[chan];
    const float s     = g_ss[b];
    const float z     = g_zz[b];
    const float inv_s = 1.0f / s;

    const float4* p = x   + (size_t)chan * (HW / 4);
    float4*       q = out + (size_t)chan * (HW / 4);
    const int t = threadIdx.x;
#pragma unroll
    for (int i = 0; i < HW / 4 / 256; ++i) {
        float4 v = p[t + i * 256];
        float4 r;
        r.x = fakequant1(v.x, sc, s, inv_s, z);
        r.y = fakequant1(v.y, sc, s, inv_s, z);
        r.z = fakequant1(v.z, sc, s, inv_s, z);
        r.w = fakequant1(v.w, sc, s, inv_s, z);
        q[t + i * 256] = r;
    }
}

// ---------------------------------------------------------------------------
extern "C" void kernel_launch(void* const* d_in, const int* in_sizes, int n_in,
                              void* d_out, int out_size) {
    const float* x              = (const float*)d_in[0];
    const float* w1             = (const float*)d_in[1];
    const float* b1             = (const float*)d_in[2];
    const float* w2             = (const float*)d_in[3];
    const float* b2             = (const float*)d_in[4];
    const float* act_range      = (const float*)d_in[5];
    const int*   sample_cluster = (const int*)d_in[6];

    k_stats<<<NCHAN, 256>>>((const float4*)x);
    k_se<<<BB, 256>>>(w1, b1, w2, b2);
    k_qparams<<<1, 64>>>(sample_cluster, act_range);
    k_quant<<<NCHAN, 256>>>((const float4*)x, (float4*)d_out);
}

// round 2
// speedup vs baseline: 1.0357x; 1.0357x over previous
#include <cuda_runtime.h>
#include <math_constants.h>

// Problem shape (fixed by dataset)
#define BB    64
#define CC    256
#define CS    64
#define HW    4096      // 64*64
#define NC    8
#define NCHAN (BB*CC)   // 16384

// Scratch (no allocations allowed)
__device__ float g_pooled[NCHAN];
__device__ float g_chmin[NCHAN];
__device__ float g_chmax[NCHAN];
__device__ float g_scale[NCHAN];
__device__ float g_smin[BB];
__device__ float g_smax[BB];

// ---------------------------------------------------------------------------
// Kernel 1: per-channel sum/min/max of x.  One block per (b,c) channel.
// Ascending channel order -> tail of x stays resident in L2 for k_quant.
// Independent 4-lane accumulators for ILP.
// ---------------------------------------------------------------------------
__global__ __launch_bounds__(256) void k_stats(const float4* __restrict__ x) {
    const int chan = blockIdx.x;
    const float4* p = x + (size_t)chan * (HW / 4);
    const int t = threadIdx.x;

    float4 mn4 = make_float4( CUDART_INF_F,  CUDART_INF_F,  CUDART_INF_F,  CUDART_INF_F);
    float4 mx4 = make_float4(-CUDART_INF_F, -CUDART_INF_F, -CUDART_INF_F, -CUDART_INF_F);
    float4 sm4 = make_float4(0.f, 0.f, 0.f, 0.f);
#pragma unroll
    for (int i = 0; i < HW / 4 / 256; ++i) {
        float4 v = p[t + i * 256];
        mn4.x = fminf(mn4.x, v.x); mn4.y = fminf(mn4.y, v.y);
        mn4.z = fminf(mn4.z, v.z); mn4.w = fminf(mn4.w, v.w);
        mx4.x = fmaxf(mx4.x, v.x); mx4.y = fmaxf(mx4.y, v.y);
        mx4.z = fmaxf(mx4.z, v.z); mx4.w = fmaxf(mx4.w, v.w);
        sm4.x += v.x; sm4.y += v.y; sm4.z += v.z; sm4.w += v.w;
    }
    float mn = fminf(fminf(mn4.x, mn4.y), fminf(mn4.z, mn4.w));
    float mx = fmaxf(fmaxf(mx4.x, mx4.y), fmaxf(mx4.z, mx4.w));
    float s  = (sm4.x + sm4.y) + (sm4.z + sm4.w);

#pragma unroll
    for (int off = 16; off; off >>= 1) {
        s  += __shfl_xor_sync(0xffffffffu, s, off);
        mn  = fminf(mn, __shfl_xor_sync(0xffffffffu, mn, off));
        mx  = fmaxf(mx, __shfl_xor_sync(0xffffffffu, mx, off));
    }
    __shared__ float ws[8], wmn[8], wmx[8];
    if ((t & 31) == 0) { ws[t >> 5] = s; wmn[t >> 5] = mn; wmx[t >> 5] = mx; }
    __syncthreads();
    if (t == 0) {
        float S = 0.0f, MN = CUDART_INF_F, MX = -CUDART_INF_F;
#pragma unroll
        for (int j = 0; j < 8; ++j) {
            S += ws[j];
            MN = fminf(MN, wmn[j]);
            MX = fmaxf(MX, wmx[j]);
        }
        g_pooled[chan] = S * (1.0f / (float)HW);   // /4096 exact (pow2)
        g_chmin[chan]  = MN;
        g_chmax[chan]  = MX;
    }
}

// ---------------------------------------------------------------------------
// Kernel 2: SE MLP + hardsigmoid + per-sample min/max of out=scale*x.
// One block (256 thr = 8 warps) per batch sample.  All weight loads are
// lane-contiguous (coalesced) + warp shuffle reductions.
// ---------------------------------------------------------------------------
__global__ __launch_bounds__(256) void k_se(const float* __restrict__ w1,
                                            const float* __restrict__ b1,
                                            const float* __restrict__ w2,
                                            const float* __restrict__ b2) {
    const int b    = blockIdx.x;
    const int t    = threadIdx.x;
    const int w    = t >> 5;      // warp id 0..7
    const int lane = t & 31;

    __shared__ float sp[CC];      // pooled
    __shared__ float sh[CS];      // hidden
    __shared__ float ssc[CC];     // scale
    sp[t] = g_pooled[b * CC + t];
    __syncthreads();

    // GEMM1: h[s] = relu(sum_c pooled[c]*w1[s,c] + b1[s]).  Warp per s.
#pragma unroll
    for (int j = 0; j < 8; ++j) {
        const int si = w * 8 + j;
        const float* row = w1 + si * CC;
        float a = 0.0f;
#pragma unroll
        for (int k = 0; k < 8; ++k)
            a = fmaf(row[lane + 32 * k], sp[lane + 32 * k], a);
#pragma unroll
        for (int off = 16; off; off >>= 1)
            a += __shfl_xor_sync(0xffffffffu, a, off);
        if (lane == 0) sh[si] = fmaxf(a + b1[si], 0.0f);
    }
    __syncthreads();

    // GEMM2: v[c] = sum_s h[s]*w2[c,s] + b2[c].  Warp per c (32 c's/warp).
#pragma unroll 4
    for (int j = 0; j < 32; ++j) {
        const int c = w * 32 + j;
        const float* row = w2 + c * CS;
        float a = fmaf(row[lane], sh[lane], row[lane + 32] * sh[lane + 32]);
#pragma unroll
        for (int off = 16; off; off >>= 1)
            a += __shfl_xor_sync(0xffffffffu, a, off);
        if (lane == 0) {
            float v = a + b2[c];
            ssc[c] = fminf(fmaxf(v / 6.0f + 0.5f, 0.0f), 1.0f);  // hardsigmoid
        }
    }
    __syncthreads();

    const float sc = ssc[t];
    g_scale[b * CC + t] = sc;

    // per-sample min/max of out (sc >= 0 => min/max factor through)
    float cmn = sc * g_chmin[b * CC + t];
    float cmx = sc * g_chmax[b * CC + t];
#pragma unroll
    for (int off = 16; off; off >>= 1) {
        cmn = fminf(cmn, __shfl_xor_sync(0xffffffffu, cmn, off));
        cmx = fmaxf(cmx, __shfl_xor_sync(0xffffffffu, cmx, off));
    }
    __shared__ float rmn[8], rmx[8];
    if (lane == 0) { rmn[w] = cmn; rmx[w] = cmx; }
    __syncthreads();
    if (t == 0) {
        float MN = CUDART_INF_F, MX = -CUDART_INF_F;
#pragma unroll
        for (int j = 0; j < 8; ++j) {
            MN = fminf(MN, rmn[j]);
            MX = fmaxf(MX, rmx[j]);
        }
        g_smin[b] = MN;
        g_smax[b] = MX;
    }
}

// ---------------------------------------------------------------------------
// Kernel 3: fused qparams + scale + fake-quant.
// Processes channels in REVERSE order so the first waves hit the tail of x
// still resident in L2 from k_stats.  Each block derives its own sample's
// (s, z) from the 64 per-sample min/max scalars (warp 0, overlapped with the
// in-flight x loads).  Streaming (.cs) loads/stores to avoid polluting L2.
// ---------------------------------------------------------------------------
__device__ __forceinline__ float fakequant1(float xv, float sc, float s,
                                            float inv_s, float z) {
    float o = sc * xv;
    float d = o * inv_s;
    d = fmaf(fmaf(-s, d, o), inv_s, d);           // refine o/s (faithful)
    float q = fminf(fmaxf(rintf(d + z), 0.0f), 255.0f);
    return (q - z) * s;
}

__global__ __launch_bounds__(256) void k_quant(const float4* __restrict__ x,
                                               float4* __restrict__ out,
                                               const int* __restrict__ sample_cluster,
                                               const float* __restrict__ act_range) {
    const int chan = (NCHAN - 1) - blockIdx.x;    // reverse order
    const int b    = chan >> 8;                   // chan / CC
    const int t    = threadIdx.x;

    const float4* p = x   + (size_t)chan * (HW / 4);
    float4*       q = out + (size_t)chan * (HW / 4);

    // Issue all x loads first (they overlap with the qparams computation).
    float4 v0 = __ldcs(p + t);
    float4 v1 = __ldcs(p + t + 256);
    float4 v2 = __ldcs(p + t + 512);
    float4 v3 = __ldcs(p + t + 768);

    __shared__ float sh_s, sh_z, sh_inv;
    if (t < 32) {
        const int myk = sample_cluster[b];
        const int c0 = sample_cluster[t];
        const int c1 = sample_cluster[t + 32];
        float mn = (c0 == myk) ? g_smin[t]      :  CUDART_INF_F;
        float mx = (c0 == myk) ? g_smax[t]      : -CUDART_INF_F;
        float n1 = (c1 == myk) ? g_smin[t + 32] :  CUDART_INF_F;
        float x1 = (c1 == myk) ? g_smax[t + 32] : -CUDART_INF_F;
        mn = fminf(mn, n1);
        mx = fmaxf(mx, x1);
#pragma unroll
        for (int off = 16; off; off >>= 1) {
            mn = fminf(mn, __shfl_xor_sync(0xffffffffu, mn, off));
            mx = fmaxf(mx, __shfl_xor_sync(0xffffffffu, mx, off));
        }
        if (t == 0) {
            float nm = act_range[2 * myk]     * 0.995f + mn * (1.0f - 0.995f);
            float nM = act_range[2 * myk + 1] * 0.995f + mx * (1.0f - 0.995f);
            float s  = (nM - nm) / 255.0f;
            sh_s   = s;
            sh_z   = -rintf(nm / s);
            sh_inv = 1.0f / s;
        }
    }
    const float sc = g_scale[chan];
    __syncthreads();
    const float s     = sh_s;
    const float z     = sh_z;
    const float inv_s = sh_inv;

    float4 r;
    r.x = fakequant1(v0.x, sc, s, inv_s, z);
    r.y = fakequant1(v0.y, sc, s, inv_s, z);
    r.z = fakequant1(v0.z, sc, s, inv_s, z);
    r.w = fakequant1(v0.w, sc, s, inv_s, z);
    __stcs(q + t, r);
    r.x = fakequant1(v1.x, sc, s, inv_s, z);
    r.y = fakequant1(v1.y, sc, s, inv_s, z);
    r.z = fakequant1(v1.z, sc, s, inv_s, z);
    r.w = fakequant1(v1.w, sc, s, inv_s, z);
    __stcs(q + t + 256, r);
    r.x = fakequant1(v2.x, sc, s, inv_s, z);
    r.y = fakequant1(v2.y, sc, s, inv_s, z);
    r.z = fakequant1(v2.z, sc, s, inv_s, z);
    r.w = fakequant1(v2.w, sc, s, inv_s, z);
    __stcs(q + t + 512, r);
    r.x = fakequant1(v3.x, sc, s, inv_s, z);
    r.y = fakequant1(v3.y, sc, s, inv_s, z);
    r.z = fakequant1(v3.z, sc, s, inv_s, z);
    r.w = fakequant1(v3.w, sc, s, inv_s, z);
    __stcs(q + t + 768, r);
}

// ---------------------------------------------------------------------------
extern "C" void kernel_launch(void* const* d_in, const int* in_sizes, int n_in,
                              void* d_out, int out_size) {
    const float* x              = (const float*)d_in[0];
    const float* w1             = (const float*)d_in[1];
    const float* b1             = (const float*)d_in[2];
    const float* w2             = (const float*)d_in[3];
    const float* b2             = (const float*)d_in[4];
    const float* act_range      = (const float*)d_in[5];
    const int*   sample_cluster = (const int*)d_in[6];

    k_stats<<<NCHAN, 256>>>((const float4*)x);
    k_se<<<BB, 256>>>(w1, b1, w2, b2);
    k_quant<<<NCHAN, 256>>>((const float4*)x, (float4*)d_out,
                            sample_cluster, act_range);
}